// round 4
// baseline (speedup 1.0000x reference)
#include <cuda_runtime.h>
#include <cuda_bf16.h>
#include <cstddef>

// hungarian_matcher cost kernel
// out[b, q, j] = 5 * sum_d |pred_boxes[b,q,d] - target_boxes[b*64+j, d]|
//              - softmax(pred_logits[b,q,:])[target_ids[b*64+j]]
//
// Shapes: pred_logits (16,900,4) f32, pred_boxes (16,900,11) f32,
//         target_boxes (1024,11) f32, target_ids (1024,) i32,
//         out (16,900,64) f32.
//
// R3 layout (resubmit after infra failure): block = 64 threads = 16 j-quads
// x 4 qy. Each thread holds 4 target boxes (44 floats) in registers via 11
// aligned LDG.128 (quad base = jq*176B), and produces QPT=3 query rows x 4
// targets = 12 outputs, written as 3x STG.128. Pred boxes staged in smem
// padded to 12 floats/row so each query row is 3 conflict-free broadcast
// LDS.128. Grid (75, 16) = 1200 CTAs -> ~8 CTAs/SM, one wave.

namespace {

constexpr int BOX  = 11;
constexpr int BOXP = 12;  // padded row
constexpr int NC   = 4;
constexpr int PER  = 64;
constexpr int QPT  = 3;   // queries per thread
constexpr int WY   = 4;   // qy threads
constexpr int QT   = WY * QPT;  // 12 queries per CTA (900 % 12 == 0)
constexpr int NT   = 16 * WY;   // 64 threads

__global__ __launch_bounds__(NT)
void matcher_kernel(const float* __restrict__ logits,
                    const float* __restrict__ boxes,
                    const float* __restrict__ tboxes,
                    const int*   __restrict__ tids,
                    float* __restrict__ out,
                    int nq)
{
    const int b  = blockIdx.y;
    const int q0 = blockIdx.x * QT;
    const int t  = threadIdx.x;
    const int jq = t & 15;        // j-quad index 0..15
    const int qy = t >> 4;        // 0..3

    __shared__ float s_pb[QT * BOXP];      // padded pred boxes
    __shared__ float s_negprob[QT * NC];   // -softmax rows

    // --- Target boxes for this thread's 4 targets: 11 aligned LDG.128 ---
    float tbf[4 * BOX];
    {
        const float4* src = (const float4*)(tboxes + ((size_t)b * PER + jq * 4) * BOX);
#pragma unroll
        for (int k = 0; k < 11; k++) ((float4*)tbf)[k] = src[k];
    }
    // Class ids for the 4 targets (coalesced LDG.128 across jq)
    const int4 c4 = ((const int4*)(tids + b * PER))[jq];
    const int* cp = (const int*)&c4;

    // --- Stage pred boxes into padded smem rows (132 elems, 64 threads) ---
    for (int i = t; i < QT * BOX; i += NT) {
        const int row = i / BOX, col = i - row * BOX;
        const int q = q0 + row;
        s_pb[row * BOXP + col] = (q < nq)
            ? boxes[((size_t)b * nq + q) * BOX + col] : 0.0f;
    }

    // --- Softmax rows: thread t < QT handles query q0+t ---
    if (t < QT) {
        const int q = q0 + t;
        float neg[NC] = {0.f, 0.f, 0.f, 0.f};
        if (q < nq) {
            const float* lp = logits + ((size_t)b * nq + q) * NC;
            float l[NC];
            float m = -1e30f;
#pragma unroll
            for (int c = 0; c < NC; c++) { l[c] = lp[c]; m = fmaxf(m, l[c]); }
            float s = 0.0f;
#pragma unroll
            for (int c = 0; c < NC; c++) { l[c] = __expf(l[c] - m); s += l[c]; }
            const float inv = __frcp_rn(s);
#pragma unroll
            for (int c = 0; c < NC; c++) neg[c] = -l[c] * inv;
        }
#pragma unroll
        for (int c = 0; c < NC; c++) s_negprob[t * NC + c] = neg[c];
    }

    __syncthreads();

    // --- 3 query rows, 4 targets each ---
#pragma unroll
    for (int k = 0; k < QPT; k++) {
        const int ql = qy * QPT + k;
        const int q  = q0 + ql;

        // Pred box row: 3 broadcast LDS.128 (row base 48B-aligned)
        float pbf[BOXP];
#pragma unroll
        for (int v = 0; v < 3; v++)
            ((float4*)pbf)[v] = ((const float4*)(s_pb + ql * BOXP))[v];

        float4 r;
        float* rp = (float*)&r;
#pragma unroll
        for (int i = 0; i < 4; i++) {
            // two accumulators to break the dependency chain
            float sa = 0.0f, sb = 0.0f;
#pragma unroll
            for (int d = 0; d < BOX; d += 2) {
                sa += fabsf(pbf[d] - tbf[i * BOX + d]);
                if (d + 1 < BOX) sb += fabsf(pbf[d + 1] - tbf[i * BOX + d + 1]);
            }
            rp[i] = fmaf(5.0f, sa + sb, s_negprob[ql * NC + cp[i]]);
        }

        if (q < nq) {
            float4* dst = (float4*)(out + ((size_t)b * nq + q) * PER + jq * 4);
            *dst = r;
        }
    }
}

} // namespace

extern "C" void kernel_launch(void* const* d_in, const int* in_sizes, int n_in,
                              void* d_out, int out_size)
{
    const float* logits = (const float*)d_in[0];
    const float* boxes  = (const float*)d_in[1];
    const float* tboxes = (const float*)d_in[2];
    const int*   tids   = (const int*)d_in[3];
    float* out = (float*)d_out;

    const int n_total = in_sizes[3];                 // 1024
    const int box_dim = in_sizes[2] / n_total;       // 11
    const int bsnq    = in_sizes[1] / box_dim;       // 14400
    const int per     = out_size / bsnq;             // 64
    const int bs      = n_total / per;               // 16
    const int nq      = bsnq / bs;                   // 900

    (void)n_in; (void)box_dim; (void)per;

    dim3 block(NT);
    dim3 grid((nq + QT - 1) / QT, bs);               // (75, 16)
    matcher_kernel<<<grid, block>>>(logits, boxes, tboxes, tids, out, nq);
}

// round 5
// speedup vs baseline: 1.0524x; 1.0524x over previous
#include <cuda_runtime.h>
#include <cuda_bf16.h>
#include <cstddef>

// hungarian_matcher cost kernel
// out[b, q, j] = 5 * sum_d |pred_boxes[b,q,d] - target_boxes[b*64+j, d]|
//              - softmax(pred_logits[b,q,:])[target_ids[b*64+j]]
//
// R5: block 256 = 32 j-pairs x 8 qy; QPT=3 -> QT=24 queries/CTA.
// grid (38,16) = 608 CTAs -> 155k threads (~51% occ), single wave.
// Targets: 2 per thread in regs via 6 LDS.128 from 12-padded smem rows.
// Pred rows: 3 broadcast LDS.128. Outputs: STG.64 (float2).

namespace {

constexpr int BOX  = 11;
constexpr int BOXP = 12;      // padded smem row (16B-aligned float4 rows)
constexpr int NC   = 4;
constexpr int PER  = 64;
constexpr int QPT  = 3;       // queries per thread
constexpr int QY   = 8;
constexpr int QT   = QY * QPT;   // 24 queries per CTA
constexpr int NT   = 32 * QY;    // 256 threads

__global__ __launch_bounds__(NT)
void matcher_kernel(const float* __restrict__ logits,
                    const float* __restrict__ boxes,
                    const float* __restrict__ tboxes,
                    const int*   __restrict__ tids,
                    float* __restrict__ out,
                    int nq)
{
    const int b  = blockIdx.y;
    const int q0 = blockIdx.x * QT;
    const int t  = threadIdx.x + threadIdx.y * 32;
    const int jp = threadIdx.x;       // j-pair 0..31 -> targets 2jp, 2jp+1
    const int qy = threadIdx.y;       // 0..7

    __shared__ float s_tb[PER * BOXP];     // 768 floats, 12-padded target boxes
    __shared__ float s_pb[QT * BOXP];      // 288 floats, 12-padded pred boxes
    __shared__ float s_negprob[QT * NC];   // 96 floats

    // --- Stage target boxes (704 src elems -> padded rows; coalesced reads) ---
    for (int i = t; i < PER * BOX; i += NT) {
        const int row = i / BOX, col = i - row * BOX;
        s_tb[row * BOXP + col] = tboxes[(size_t)b * PER * BOX + i];
    }

    // --- Stage pred boxes for this query tile (guarded; zeros past nq) ---
    for (int i = t; i < QT * BOX; i += NT) {
        const int row = i / BOX, col = i - row * BOX;
        const int q = q0 + row;
        s_pb[row * BOXP + col] = (q < nq)
            ? boxes[((size_t)b * nq + q) * BOX + col] : 0.0f;
    }

    // --- Softmax rows: thread t < QT handles query q0+t ---
    if (t < QT) {
        const int q = q0 + t;
        float neg[NC] = {0.f, 0.f, 0.f, 0.f};
        if (q < nq) {
            const float* lp = logits + ((size_t)b * nq + q) * NC;
            float l[NC];
            float m = -1e30f;
#pragma unroll
            for (int c = 0; c < NC; c++) { l[c] = lp[c]; m = fmaxf(m, l[c]); }
            float s = 0.0f;
#pragma unroll
            for (int c = 0; c < NC; c++) { l[c] = __expf(l[c] - m); s += l[c]; }
            const float inv = __frcp_rn(s);
#pragma unroll
            for (int c = 0; c < NC; c++) neg[c] = -l[c] * inv;
        }
#pragma unroll
        for (int c = 0; c < NC; c++) s_negprob[t * NC + c] = neg[c];
    }

    // Class ids for this thread's 2 targets (aligned int2, coalesced)
    const int2 cls = *(const int2*)(tids + b * PER + 2 * jp);

    __syncthreads();

    // --- Target pair to registers: 6 LDS.128 (12-pad rows; mild 2-way conflict) ---
    float tb0[BOXP], tb1[BOXP];
    {
        const float4* r0 = (const float4*)(s_tb + (2 * jp + 0) * BOXP);
        const float4* r1 = (const float4*)(s_tb + (2 * jp + 1) * BOXP);
#pragma unroll
        for (int v = 0; v < 3; v++) {
            ((float4*)tb0)[v] = r0[v];
            ((float4*)tb1)[v] = r1[v];
        }
    }

    // --- 3 query rows, 2 targets each, float2 stores ---
#pragma unroll
    for (int k = 0; k < QPT; k++) {
        const int ql = qy * QPT + k;
        const int q  = q0 + ql;

        float pbf[BOXP];
#pragma unroll
        for (int v = 0; v < 3; v++)
            ((float4*)pbf)[v] = ((const float4*)(s_pb + ql * BOXP))[v];

        float s0a = 0.f, s0b = 0.f, s1a = 0.f, s1b = 0.f;
#pragma unroll
        for (int d = 0; d < BOX; d += 2) {
            s0a += fabsf(pbf[d] - tb0[d]);
            s1a += fabsf(pbf[d] - tb1[d]);
            if (d + 1 < BOX) {
                s0b += fabsf(pbf[d + 1] - tb0[d + 1]);
                s1b += fabsf(pbf[d + 1] - tb1[d + 1]);
            }
        }

        float2 r;
        r.x = fmaf(5.0f, s0a + s0b, s_negprob[ql * NC + cls.x]);
        r.y = fmaf(5.0f, s1a + s1b, s_negprob[ql * NC + cls.y]);

        if (q < nq) {
            *(float2*)(out + ((size_t)b * nq + q) * PER + 2 * jp) = r;
        }
    }
}

} // namespace

extern "C" void kernel_launch(void* const* d_in, const int* in_sizes, int n_in,
                              void* d_out, int out_size)
{
    const float* logits = (const float*)d_in[0];
    const float* boxes  = (const float*)d_in[1];
    const float* tboxes = (const float*)d_in[2];
    const int*   tids   = (const int*)d_in[3];
    float* out = (float*)d_out;

    const int n_total = in_sizes[3];                 // 1024
    const int box_dim = in_sizes[2] / n_total;       // 11
    const int bsnq    = in_sizes[1] / box_dim;       // 14400
    const int per     = out_size / bsnq;             // 64
    const int bs      = n_total / per;               // 16
    const int nq      = bsnq / bs;                   // 900

    (void)n_in; (void)box_dim; (void)per;

    dim3 block(32, QY);
    dim3 grid((nq + QT - 1) / QT, bs);               // (38, 16)
    matcher_kernel<<<grid, block>>>(logits, boxes, tboxes, tids, out, nq);
}

// round 7
// speedup vs baseline: 1.0977x; 1.0430x over previous
#include <cuda_runtime.h>
#include <cuda_bf16.h>
#include <cstddef>

// hungarian_matcher cost kernel
// out[b, q, j] = 5 * sum_d |pred_boxes[b,q,d] - target_boxes[b*64+j, d]|
//              - softmax(pred_logits[b,q,:])[target_ids[b*64+j]]
//
// R6 (resubmit after infra failure) = R2 (best measured: block (64,4),
// QT=20, QPT=5, grid (45,16)=720) with the target-box load path fixed:
// instead of 11 scalar LDGs at 44B lane-stride per thread (~11 cache lines
// PER LDG instruction -> L1tex wavefront storm), targets are staged
// coalesced via float4 LDG/STS into an unpadded stride-11 smem tile, then
// read as 11 scalar LDS at stride 11 per thread (gcd(11,32)=1 ->
// conflict-free).

namespace {

constexpr int BOX = 11;
constexpr int NC  = 4;
constexpr int PER = 64;
constexpr int QT  = 20;   // queries per CTA (900 = 45*20)
constexpr int QPT = 5;    // queries per thread
constexpr int NT  = PER * 4;  // 256 threads

__global__ __launch_bounds__(NT)
void matcher_kernel(const float* __restrict__ logits,
                    const float* __restrict__ boxes,
                    const float* __restrict__ tboxes,
                    const int*   __restrict__ tids,
                    float* __restrict__ out,
                    int nq)
{
    const int b  = blockIdx.y;
    const int q0 = blockIdx.x * QT;
    const int j  = threadIdx.x;           // target 0..63
    const int qy = threadIdx.y;           // 0..3
    const int t  = qy * PER + j;          // linear tid

    __shared__ float s_tb[PER * BOX];          // 704 floats, stride-11 rows
    __shared__ float s_pb[QT * BOX];           // 220 floats
    __shared__ float s_negprob[QT * NC];       // 80 floats

    // --- Target boxes: coalesced float4 staging (176 lanes, one shot) ---
    {
        const float4* src = (const float4*)(tboxes + (size_t)b * PER * BOX);
        if (t < PER * BOX / 4) ((float4*)s_tb)[t] = src[t];
    }

    // --- Pred boxes for this tile: 220 floats, coalesced ---
    if (t < QT * BOX) {
        s_pb[t] = boxes[((size_t)b * nq + q0) * BOX + t];
    }

    // --- Softmax rows: thread t < QT handles query q0+t ---
    if (t < QT) {
        const float* lp = logits + ((size_t)b * nq + q0 + t) * NC;
        float l[NC];
        float m = -1e30f;
#pragma unroll
        for (int c = 0; c < NC; c++) { l[c] = lp[c]; m = fmaxf(m, l[c]); }
        float s = 0.0f;
#pragma unroll
        for (int c = 0; c < NC; c++) { l[c] = __expf(l[c] - m); s += l[c]; }
        const float inv = __frcp_rn(s);
#pragma unroll
        for (int c = 0; c < NC; c++) s_negprob[t * NC + c] = -l[c] * inv;
    }

    // Class id (coalesced 4B LDG across j, L1-resident)
    const int cls = tids[b * PER + j];

    __syncthreads();

    // --- Target box -> registers: 11 LDS, stride 11, conflict-free ---
    float tb[BOX];
#pragma unroll
    for (int d = 0; d < BOX; d++) tb[d] = s_tb[j * BOX + d];

    // --- 5 query rows; pred-box LDS are warp-uniform broadcasts ---
    float* orow = out + ((size_t)b * nq + q0 + qy * QPT) * PER + j;
#pragma unroll
    for (int k = 0; k < QPT; k++) {
        const int ql = qy * QPT + k;
        float sa = 0.0f, sb = 0.0f;
#pragma unroll
        for (int d = 0; d < BOX; d += 2) {
            sa += fabsf(s_pb[ql * BOX + d] - tb[d]);
            if (d + 1 < BOX) sb += fabsf(s_pb[ql * BOX + d + 1] - tb[d + 1]);
        }
        orow[(size_t)k * PER] = fmaf(5.0f, sa + sb, s_negprob[ql * NC + cls]);
    }
}

} // namespace

extern "C" void kernel_launch(void* const* d_in, const int* in_sizes, int n_in,
                              void* d_out, int out_size)
{
    const float* logits = (const float*)d_in[0];
    const float* boxes  = (const float*)d_in[1];
    const float* tboxes = (const float*)d_in[2];
    const int*   tids   = (const int*)d_in[3];
    float* out = (float*)d_out;

    const int n_total = in_sizes[3];                 // 1024
    const int box_dim = in_sizes[2] / n_total;       // 11
    const int bsnq    = in_sizes[1] / box_dim;       // 14400
    const int per     = out_size / bsnq;             // 64
    const int bs      = n_total / per;               // 16
    const int nq      = bsnq / bs;                   // 900

    (void)n_in; (void)box_dim; (void)per;

    dim3 block(PER, 4);
    dim3 grid(nq / QT, bs);                          // (45, 16) = 720
    matcher_kernel<<<grid, block>>>(logits, boxes, tboxes, tids, out, nq);
}